// round 7
// baseline (speedup 1.0000x reference)
#include <cuda_runtime.h>
#include <math.h>

#define BATCH 4
#define SEQ   2048
#define DMODEL 512
#define NHEADS 8
#define DHEAD  64
#define MROWS (BATCH*SEQ)   // 8192

// Scratch (allocation-free rule: __device__ globals)
__device__ float g_q[BATCH*NHEADS*SEQ*DHEAD];   // [B,H,S,Dh]
__device__ float g_k[BATCH*NHEADS*SEQ*DHEAD];
__device__ float g_v[BATCH*NHEADS*SEQ*DHEAD];
__device__ float g_att[BATCH*SEQ*DMODEL];       // [B,S,D]

// ---------------------------------------------------------------------------
// GEMM: out = A[M,512] @ W[512,512] + bias
// MODE 0: out[m*512+n]   (plain, for O-projection into d_out)
// MODE 1: head-split scatter for Q/K/V: out[((b*H+h)*S+s)*64 + d]
// Tile: BM=128, BN=64, BK=32, 256 threads, 8x4 microtile per thread.
// ---------------------------------------------------------------------------
template<int MODE>
__global__ __launch_bounds__(256)
void gemm512(const float* __restrict__ A, const float* __restrict__ W,
             const float* __restrict__ bias, float* __restrict__ out)
{
    constexpr int BM = 128, BN = 64, BK = 32;
    __shared__ float As[BK][BM];   // transposed A tile
    __shared__ float Bs[BK][BN];

    const int tid = threadIdx.x;
    const int block_n = blockIdx.x * BN;
    const int block_m = blockIdx.y * BM;

    const int tn = (tid & 15) * 4;       // 0..60
    const int tm = (tid >> 4) * 8;       // 0..120

    const int a_row  = tid >> 3;         // 0..31 (then +i*32)
    const int a_col4 = (tid & 7) * 4;    // k offset 0..28
    const int b_row  = tid >> 4;         // 0..15 (then +i*16)
    const int b_col4 = (tid & 15) * 4;

    float acc[8][4];
    #pragma unroll
    for (int i = 0; i < 8; i++)
        #pragma unroll
        for (int j = 0; j < 4; j++) acc[i][j] = 0.f;

    for (int k0 = 0; k0 < DMODEL; k0 += BK) {
        __syncthreads();
        #pragma unroll
        for (int i = 0; i < 4; i++) {
            int m = a_row + i * 32;
            float4 v = *(const float4*)&A[(size_t)(block_m + m) * DMODEL + k0 + a_col4];
            As[a_col4 + 0][m] = v.x;
            As[a_col4 + 1][m] = v.y;
            As[a_col4 + 2][m] = v.z;
            As[a_col4 + 3][m] = v.w;
        }
        #pragma unroll
        for (int i = 0; i < 2; i++) {
            int kk = b_row + i * 16;
            *(float4*)&Bs[kk][b_col4] =
                *(const float4*)&W[(size_t)(k0 + kk) * DMODEL + block_n + b_col4];
        }
        __syncthreads();

        #pragma unroll
        for (int kk = 0; kk < BK; kk++) {
            float a[8], bf[4];
            *(float4*)&a[0] = *(const float4*)&As[kk][tm];
            *(float4*)&a[4] = *(const float4*)&As[kk][tm + 4];
            *(float4*)&bf[0] = *(const float4*)&Bs[kk][tn];
            #pragma unroll
            for (int i = 0; i < 8; i++)
                #pragma unroll
                for (int j = 0; j < 4; j++)
                    acc[i][j] = fmaf(a[i], bf[j], acc[i][j]);
        }
    }

    #pragma unroll
    for (int i = 0; i < 8; i++) {
        int m = block_m + tm + i;
        #pragma unroll
        for (int j = 0; j < 4; j++) {
            int n = block_n + tn + j;
            float val = acc[i][j] + bias[n];
            if (MODE == 0) {
                out[(size_t)m * DMODEL + n] = val;
            } else {
                int b = m / SEQ, s = m % SEQ;
                int h = n / DHEAD, d = n % DHEAD;
                out[(((size_t)(b * NHEADS + h)) * SEQ + s) * DHEAD + d] = val;
            }
        }
    }
}

// ---------------------------------------------------------------------------
// Flash-attention (streaming softmax), fp32.
// grid: (S/BQ, B*H), block: 256 threads.
// 2 threads per query row; each owns 32 of 64 output dims; Q row half + scores
// + output accumulators in registers; K/V tiles in SMEM (broadcast-friendly).
// Output written directly in [B,S,D] layout into g_att.
// ---------------------------------------------------------------------------
#define BQ 128
#define BKK 32

__global__ __launch_bounds__(256)
void attn_kernel(float* __restrict__ out)
{
    const int bh = blockIdx.y;             // 0..31
    const int b = bh / NHEADS, h = bh % NHEADS;
    const int q0 = blockIdx.x * BQ;
    const int tid = threadIdx.x;
    const int row = tid >> 1;              // 0..127
    const int hf  = tid & 1;               // half of Dh

    const float* Qbase = g_q + ((size_t)bh * SEQ + q0) * DHEAD;
    const float* Kbase = g_k + (size_t)bh * SEQ * DHEAD;
    const float* Vbase = g_v + (size_t)bh * SEQ * DHEAD;

    __shared__ float Ks[BKK][DHEAD];
    __shared__ float Vs[BKK][DHEAD];

    float qreg[32];
    #pragma unroll
    for (int i = 0; i < 8; i++)
        *(float4*)&qreg[i * 4] =
            *(const float4*)&Qbase[(size_t)row * DHEAD + hf * 32 + i * 4];

    float o[32];
    #pragma unroll
    for (int i = 0; i < 32; i++) o[i] = 0.f;
    float mrow = -1e30f, lrow = 0.f;
    const float scale = 0.04419417382415922f;   // 1/sqrt(512)

    for (int kb = 0; kb < SEQ; kb += BKK) {
        __syncthreads();
        // load K,V tile: 32x64 floats each -> 512 float4 each, 2 per thread
        #pragma unroll
        for (int i = 0; i < 2; i++) {
            int idx = tid + i * 256;       // float4 index 0..511
            int r = idx >> 4;              // 16 float4 per row
            int c = (idx & 15) * 4;
            *(float4*)&Ks[r][c] = *(const float4*)&Kbase[(size_t)(kb + r) * DHEAD + c];
            *(float4*)&Vs[r][c] = *(const float4*)&Vbase[(size_t)(kb + r) * DHEAD + c];
        }
        __syncthreads();

        float sc[BKK];
        float mblk = -1e30f;
        #pragma unroll
        for (int j = 0; j < BKK; j++) {
            float p = 0.f;
            #pragma unroll
            for (int d4 = 0; d4 < 8; d4++) {
                float4 kv = *(const float4*)&Ks[j][hf * 32 + d4 * 4];
                p = fmaf(qreg[d4*4+0], kv.x, p);
                p = fmaf(qreg[d4*4+1], kv.y, p);
                p = fmaf(qreg[d4*4+2], kv.z, p);
                p = fmaf(qreg[d4*4+3], kv.w, p);
            }
            p += __shfl_xor_sync(0xffffffffu, p, 1);   // combine the two halves
            p *= scale;
            sc[j] = p;
            mblk = fmaxf(mblk, p);
        }

        float mnew = fmaxf(mrow, mblk);
        float corr = __expf(mrow - mnew);
        lrow *= corr;
        #pragma unroll
        for (int i = 0; i < 32; i++) o[i] *= corr;

        #pragma unroll
        for (int j = 0; j < BKK; j++) {
            float p = __expf(sc[j] - mnew);
            lrow += p;
            #pragma unroll
            for (int d4 = 0; d4 < 8; d4++) {
                float4 vv = *(const float4*)&Vs[j][hf * 32 + d4 * 4];
                o[d4*4+0] = fmaf(p, vv.x, o[d4*4+0]);
                o[d4*4+1] = fmaf(p, vv.y, o[d4*4+1]);
                o[d4*4+2] = fmaf(p, vv.z, o[d4*4+2]);
                o[d4*4+3] = fmaf(p, vv.w, o[d4*4+3]);
            }
        }
        mrow = mnew;
    }

    const float inv = 1.f / lrow;
    const int qrow = q0 + row;
    float* obase = out + ((size_t)(b * SEQ + qrow)) * DMODEL + h * DHEAD + hf * 32;
    #pragma unroll
    for (int i = 0; i < 8; i++) {
        float4 vv = make_float4(o[i*4+0]*inv, o[i*4+1]*inv, o[i*4+2]*inv, o[i*4+3]*inv);
        *(float4*)&obase[i * 4] = vv;
    }
}

// ---------------------------------------------------------------------------

extern "C" void kernel_launch(void* const* d_in, const int* in_sizes, int n_in,
                              void* d_out, int out_size)
{
    (void)in_sizes; (void)n_in; (void)out_size;
    const float* x  = (const float*)d_in[0];
    const float* Wq = (const float*)d_in[1];
    const float* bq = (const float*)d_in[2];
    const float* Wk = (const float*)d_in[3];
    const float* bk = (const float*)d_in[4];
    const float* Wv = (const float*)d_in[5];
    const float* bv = (const float*)d_in[6];
    const float* Wo = (const float*)d_in[7];
    const float* bo = (const float*)d_in[8];
    float* out = (float*)d_out;

    float *pq, *pk, *pv, *patt;
    cudaGetSymbolAddress((void**)&pq,   g_q);
    cudaGetSymbolAddress((void**)&pk,   g_k);
    cudaGetSymbolAddress((void**)&pv,   g_v);
    cudaGetSymbolAddress((void**)&patt, g_att);

    dim3 gemm_grid(DMODEL / 64, MROWS / 128);   // (8, 64)
    gemm512<1><<<gemm_grid, 256>>>(x, Wq, bq, pq);
    gemm512<1><<<gemm_grid, 256>>>(x, Wk, bk, pk);
    gemm512<1><<<gemm_grid, 256>>>(x, Wv, bv, pv);

    dim3 attn_grid(SEQ / BQ, BATCH * NHEADS);   // (16, 32)
    attn_kernel<<<attn_grid, 256>>>(patt);

    gemm512<0><<<gemm_grid, 256>>>(patt, Wo, bo, out);
}

// round 8
// speedup vs baseline: 1.0008x; 1.0008x over previous
#include <cuda_runtime.h>
#include <math.h>

#define BATCH 4
#define SEQ   2048
#define DMODEL 512
#define NHEADS 8
#define DHEAD  64
#define MROWS (BATCH*SEQ)   // 8192

// Scratch (allocation-free rule: __device__ globals)
__device__ float g_q[BATCH*NHEADS*SEQ*DHEAD];   // [B,H,S,Dh]
__device__ float g_k[BATCH*NHEADS*SEQ*DHEAD];
__device__ float g_v[BATCH*NHEADS*SEQ*DHEAD];
__device__ float g_att[BATCH*SEQ*DMODEL];       // [B,S,D]

// ---------------------------------------------------------------------------
// GEMM: out = A[M,512] @ W[512,512] + bias
// MODE 0: out[m*512+n]   (plain, for O-projection into d_out)
// MODE 1: head-split scatter for Q/K/V: out[((b*H+h)*S+s)*64 + d]
// Tile: BM=128, BN=64, BK=32, 256 threads, 8x4 microtile per thread.
// ---------------------------------------------------------------------------
template<int MODE>
__global__ __launch_bounds__(256)
void gemm512(const float* __restrict__ A, const float* __restrict__ W,
             const float* __restrict__ bias, float* __restrict__ out)
{
    constexpr int BM = 128, BN = 64, BK = 32;
    __shared__ float As[BK][BM];   // transposed A tile
    __shared__ float Bs[BK][BN];

    const int tid = threadIdx.x;
    const int block_n = blockIdx.x * BN;
    const int block_m = blockIdx.y * BM;

    const int tn = (tid & 15) * 4;       // 0..60
    const int tm = (tid >> 4) * 8;       // 0..120

    const int a_row  = tid >> 3;         // 0..31 (then +i*32)
    const int a_col4 = (tid & 7) * 4;    // k offset 0..28
    const int b_row  = tid >> 4;         // 0..15 (then +i*16)
    const int b_col4 = (tid & 15) * 4;

    float acc[8][4];
    #pragma unroll
    for (int i = 0; i < 8; i++)
        #pragma unroll
        for (int j = 0; j < 4; j++) acc[i][j] = 0.f;

    for (int k0 = 0; k0 < DMODEL; k0 += BK) {
        __syncthreads();
        #pragma unroll
        for (int i = 0; i < 4; i++) {
            int m = a_row + i * 32;
            float4 v = *(const float4*)&A[(size_t)(block_m + m) * DMODEL + k0 + a_col4];
            As[a_col4 + 0][m] = v.x;
            As[a_col4 + 1][m] = v.y;
            As[a_col4 + 2][m] = v.z;
            As[a_col4 + 3][m] = v.w;
        }
        #pragma unroll
        for (int i = 0; i < 2; i++) {
            int kk = b_row + i * 16;
            *(float4*)&Bs[kk][b_col4] =
                *(const float4*)&W[(size_t)(k0 + kk) * DMODEL + block_n + b_col4];
        }
        __syncthreads();

        #pragma unroll
        for (int kk = 0; kk < BK; kk++) {
            float a[8], bf[4];
            *(float4*)&a[0] = *(const float4*)&As[kk][tm];
            *(float4*)&a[4] = *(const float4*)&As[kk][tm + 4];
            *(float4*)&bf[0] = *(const float4*)&Bs[kk][tn];
            #pragma unroll
            for (int i = 0; i < 8; i++)
                #pragma unroll
                for (int j = 0; j < 4; j++)
                    acc[i][j] = fmaf(a[i], bf[j], acc[i][j]);
        }
    }

    #pragma unroll
    for (int i = 0; i < 8; i++) {
        int m = block_m + tm + i;
        #pragma unroll
        for (int j = 0; j < 4; j++) {
            int n = block_n + tn + j;
            float val = acc[i][j] + bias[n];
            if (MODE == 0) {
                out[(size_t)m * DMODEL + n] = val;
            } else {
                int b = m / SEQ, s = m % SEQ;
                int h = n / DHEAD, d = n % DHEAD;
                out[(((size_t)(b * NHEADS + h)) * SEQ + s) * DHEAD + d] = val;
            }
        }
    }
}

// ---------------------------------------------------------------------------
// Flash-attention (streaming softmax), fp32.
// grid: (S/BQ, B*H), block: 256 threads.
// 2 threads per query row; each owns 32 of 64 output dims; Q row half + scores
// + output accumulators in registers; K/V tiles in SMEM (broadcast-friendly).
// Output written directly in [B,S,D] layout into g_att.
// ---------------------------------------------------------------------------
#define BQ 128
#define BKK 32

__global__ __launch_bounds__(256)
void attn_kernel(float* __restrict__ out)
{
    const int bh = blockIdx.y;             // 0..31
    const int b = bh / NHEADS, h = bh % NHEADS;
    const int q0 = blockIdx.x * BQ;
    const int tid = threadIdx.x;
    const int row = tid >> 1;              // 0..127
    const int hf  = tid & 1;               // half of Dh

    const float* Qbase = g_q + ((size_t)bh * SEQ + q0) * DHEAD;
    const float* Kbase = g_k + (size_t)bh * SEQ * DHEAD;
    const float* Vbase = g_v + (size_t)bh * SEQ * DHEAD;

    __shared__ float Ks[BKK][DHEAD];
    __shared__ float Vs[BKK][DHEAD];

    float qreg[32];
    #pragma unroll
    for (int i = 0; i < 8; i++)
        *(float4*)&qreg[i * 4] =
            *(const float4*)&Qbase[(size_t)row * DHEAD + hf * 32 + i * 4];

    float o[32];
    #pragma unroll
    for (int i = 0; i < 32; i++) o[i] = 0.f;
    float mrow = -1e30f, lrow = 0.f;
    const float scale = 0.04419417382415922f;   // 1/sqrt(512)

    for (int kb = 0; kb < SEQ; kb += BKK) {
        __syncthreads();
        // load K,V tile: 32x64 floats each -> 512 float4 each, 2 per thread
        #pragma unroll
        for (int i = 0; i < 2; i++) {
            int idx = tid + i * 256;       // float4 index 0..511
            int r = idx >> 4;              // 16 float4 per row
            int c = (idx & 15) * 4;
            *(float4*)&Ks[r][c] = *(const float4*)&Kbase[(size_t)(kb + r) * DHEAD + c];
            *(float4*)&Vs[r][c] = *(const float4*)&Vbase[(size_t)(kb + r) * DHEAD + c];
        }
        __syncthreads();

        float sc[BKK];
        float mblk = -1e30f;
        #pragma unroll
        for (int j = 0; j < BKK; j++) {
            float p = 0.f;
            #pragma unroll
            for (int d4 = 0; d4 < 8; d4++) {
                float4 kv = *(const float4*)&Ks[j][hf * 32 + d4 * 4];
                p = fmaf(qreg[d4*4+0], kv.x, p);
                p = fmaf(qreg[d4*4+1], kv.y, p);
                p = fmaf(qreg[d4*4+2], kv.z, p);
                p = fmaf(qreg[d4*4+3], kv.w, p);
            }
            p += __shfl_xor_sync(0xffffffffu, p, 1);   // combine the two halves
            p *= scale;
            sc[j] = p;
            mblk = fmaxf(mblk, p);
        }

        float mnew = fmaxf(mrow, mblk);
        float corr = __expf(mrow - mnew);
        lrow *= corr;
        #pragma unroll
        for (int i = 0; i < 32; i++) o[i] *= corr;

        #pragma unroll
        for (int j = 0; j < BKK; j++) {
            float p = __expf(sc[j] - mnew);
            lrow += p;
            #pragma unroll
            for (int d4 = 0; d4 < 8; d4++) {
                float4 vv = *(const float4*)&Vs[j][hf * 32 + d4 * 4];
                o[d4*4+0] = fmaf(p, vv.x, o[d4*4+0]);
                o[d4*4+1] = fmaf(p, vv.y, o[d4*4+1]);
                o[d4*4+2] = fmaf(p, vv.z, o[d4*4+2]);
                o[d4*4+3] = fmaf(p, vv.w, o[d4*4+3]);
            }
        }
        mrow = mnew;
    }

    const float inv = 1.f / lrow;
    const int qrow = q0 + row;
    float* obase = out + ((size_t)(b * SEQ + qrow)) * DMODEL + h * DHEAD + hf * 32;
    #pragma unroll
    for (int i = 0; i < 8; i++) {
        float4 vv = make_float4(o[i*4+0]*inv, o[i*4+1]*inv, o[i*4+2]*inv, o[i*4+3]*inv);
        *(float4*)&obase[i * 4] = vv;
    }
}

// ---------------------------------------------------------------------------

extern "C" void kernel_launch(void* const* d_in, const int* in_sizes, int n_in,
                              void* d_out, int out_size)
{
    (void)in_sizes; (void)n_in; (void)out_size;
    const float* x  = (const float*)d_in[0];
    const float* Wq = (const float*)d_in[1];
    const float* bq = (const float*)d_in[2];
    const float* Wk = (const float*)d_in[3];
    const float* bk = (const float*)d_in[4];
    const float* Wv = (const float*)d_in[5];
    const float* bv = (const float*)d_in[6];
    const float* Wo = (const float*)d_in[7];
    const float* bo = (const float*)d_in[8];
    float* out = (float*)d_out;

    float *pq, *pk, *pv, *patt;
    cudaGetSymbolAddress((void**)&pq,   g_q);
    cudaGetSymbolAddress((void**)&pk,   g_k);
    cudaGetSymbolAddress((void**)&pv,   g_v);
    cudaGetSymbolAddress((void**)&patt, g_att);

    dim3 gemm_grid(DMODEL / 64, MROWS / 128);   // (8, 64)
    gemm512<1><<<gemm_grid, 256>>>(x, Wq, bq, pq);
    gemm512<1><<<gemm_grid, 256>>>(x, Wk, bk, pk);
    gemm512<1><<<gemm_grid, 256>>>(x, Wv, bv, pv);

    dim3 attn_grid(SEQ / BQ, BATCH * NHEADS);   // (16, 32)
    attn_kernel<<<attn_grid, 256>>>(patt);

    gemm512<0><<<gemm_grid, 256>>>(patt, Wo, bo, out);
}

// round 9
// speedup vs baseline: 1.0010x; 1.0002x over previous
#include <cuda_runtime.h>
#include <math.h>

#define BATCH 4
#define SEQ   2048
#define DMODEL 512
#define NHEADS 8
#define DHEAD  64
#define MROWS (BATCH*SEQ)   // 8192

// Scratch (allocation-free rule: __device__ globals)
__device__ float g_q[BATCH*NHEADS*SEQ*DHEAD];   // [B,H,S,Dh]
__device__ float g_k[BATCH*NHEADS*SEQ*DHEAD];
__device__ float g_v[BATCH*NHEADS*SEQ*DHEAD];
__device__ float g_att[BATCH*SEQ*DMODEL];       // [B,S,D]

// ---------------------------------------------------------------------------
// GEMM: out = A[M,512] @ W[512,512] + bias
// MODE 0: out[m*512+n]   (plain, for O-projection into d_out)
// MODE 1: head-split scatter for Q/K/V: out[((b*H+h)*S+s)*64 + d]
// Tile: BM=128, BN=64, BK=32, 256 threads, 8x4 microtile per thread.
// ---------------------------------------------------------------------------
template<int MODE>
__global__ __launch_bounds__(256)
void gemm512(const float* __restrict__ A, const float* __restrict__ W,
             const float* __restrict__ bias, float* __restrict__ out)
{
    constexpr int BM = 128, BN = 64, BK = 32;
    __shared__ float As[BK][BM];   // transposed A tile
    __shared__ float Bs[BK][BN];

    const int tid = threadIdx.x;
    const int block_n = blockIdx.x * BN;
    const int block_m = blockIdx.y * BM;

    const int tn = (tid & 15) * 4;       // 0..60
    const int tm = (tid >> 4) * 8;       // 0..120

    const int a_row  = tid >> 3;         // 0..31 (then +i*32)
    const int a_col4 = (tid & 7) * 4;    // k offset 0..28
    const int b_row  = tid >> 4;         // 0..15 (then +i*16)
    const int b_col4 = (tid & 15) * 4;

    float acc[8][4];
    #pragma unroll
    for (int i = 0; i < 8; i++)
        #pragma unroll
        for (int j = 0; j < 4; j++) acc[i][j] = 0.f;

    for (int k0 = 0; k0 < DMODEL; k0 += BK) {
        __syncthreads();
        #pragma unroll
        for (int i = 0; i < 4; i++) {
            int m = a_row + i * 32;
            float4 v = *(const float4*)&A[(size_t)(block_m + m) * DMODEL + k0 + a_col4];
            As[a_col4 + 0][m] = v.x;
            As[a_col4 + 1][m] = v.y;
            As[a_col4 + 2][m] = v.z;
            As[a_col4 + 3][m] = v.w;
        }
        #pragma unroll
        for (int i = 0; i < 2; i++) {
            int kk = b_row + i * 16;
            *(float4*)&Bs[kk][b_col4] =
                *(const float4*)&W[(size_t)(k0 + kk) * DMODEL + block_n + b_col4];
        }
        __syncthreads();

        #pragma unroll
        for (int kk = 0; kk < BK; kk++) {
            float a[8], bf[4];
            *(float4*)&a[0] = *(const float4*)&As[kk][tm];
            *(float4*)&a[4] = *(const float4*)&As[kk][tm + 4];
            *(float4*)&bf[0] = *(const float4*)&Bs[kk][tn];
            #pragma unroll
            for (int i = 0; i < 8; i++)
                #pragma unroll
                for (int j = 0; j < 4; j++)
                    acc[i][j] = fmaf(a[i], bf[j], acc[i][j]);
        }
    }

    #pragma unroll
    for (int i = 0; i < 8; i++) {
        int m = block_m + tm + i;
        #pragma unroll
        for (int j = 0; j < 4; j++) {
            int n = block_n + tn + j;
            float val = acc[i][j] + bias[n];
            if (MODE == 0) {
                out[(size_t)m * DMODEL + n] = val;
            } else {
                int b = m / SEQ, s = m % SEQ;
                int h = n / DHEAD, d = n % DHEAD;
                out[(((size_t)(b * NHEADS + h)) * SEQ + s) * DHEAD + d] = val;
            }
        }
    }
}

// ---------------------------------------------------------------------------
// Flash-attention (streaming softmax), fp32.
// grid: (S/BQ, B*H), block: 256 threads.
// 2 threads per query row; each owns 32 of 64 output dims; Q row half + scores
// + output accumulators in registers; K/V tiles in SMEM (broadcast-friendly).
// Output written directly in [B,S,D] layout into g_att.
// ---------------------------------------------------------------------------
#define BQ 128
#define BKK 32

__global__ __launch_bounds__(256)
void attn_kernel(float* __restrict__ out)
{
    const int bh = blockIdx.y;             // 0..31
    const int b = bh / NHEADS, h = bh % NHEADS;
    const int q0 = blockIdx.x * BQ;
    const int tid = threadIdx.x;
    const int row = tid >> 1;              // 0..127
    const int hf  = tid & 1;               // half of Dh

    const float* Qbase = g_q + ((size_t)bh * SEQ + q0) * DHEAD;
    const float* Kbase = g_k + (size_t)bh * SEQ * DHEAD;
    const float* Vbase = g_v + (size_t)bh * SEQ * DHEAD;

    __shared__ float Ks[BKK][DHEAD];
    __shared__ float Vs[BKK][DHEAD];

    float qreg[32];
    #pragma unroll
    for (int i = 0; i < 8; i++)
        *(float4*)&qreg[i * 4] =
            *(const float4*)&Qbase[(size_t)row * DHEAD + hf * 32 + i * 4];

    float o[32];
    #pragma unroll
    for (int i = 0; i < 32; i++) o[i] = 0.f;
    float mrow = -1e30f, lrow = 0.f;
    const float scale = 0.04419417382415922f;   // 1/sqrt(512)

    for (int kb = 0; kb < SEQ; kb += BKK) {
        __syncthreads();
        // load K,V tile: 32x64 floats each -> 512 float4 each, 2 per thread
        #pragma unroll
        for (int i = 0; i < 2; i++) {
            int idx = tid + i * 256;       // float4 index 0..511
            int r = idx >> 4;              // 16 float4 per row
            int c = (idx & 15) * 4;
            *(float4*)&Ks[r][c] = *(const float4*)&Kbase[(size_t)(kb + r) * DHEAD + c];
            *(float4*)&Vs[r][c] = *(const float4*)&Vbase[(size_t)(kb + r) * DHEAD + c];
        }
        __syncthreads();

        float sc[BKK];
        float mblk = -1e30f;
        #pragma unroll
        for (int j = 0; j < BKK; j++) {
            float p = 0.f;
            #pragma unroll
            for (int d4 = 0; d4 < 8; d4++) {
                float4 kv = *(const float4*)&Ks[j][hf * 32 + d4 * 4];
                p = fmaf(qreg[d4*4+0], kv.x, p);
                p = fmaf(qreg[d4*4+1], kv.y, p);
                p = fmaf(qreg[d4*4+2], kv.z, p);
                p = fmaf(qreg[d4*4+3], kv.w, p);
            }
            p += __shfl_xor_sync(0xffffffffu, p, 1);   // combine the two halves
            p *= scale;
            sc[j] = p;
            mblk = fmaxf(mblk, p);
        }

        float mnew = fmaxf(mrow, mblk);
        float corr = __expf(mrow - mnew);
        lrow *= corr;
        #pragma unroll
        for (int i = 0; i < 32; i++) o[i] *= corr;

        #pragma unroll
        for (int j = 0; j < BKK; j++) {
            float p = __expf(sc[j] - mnew);
            lrow += p;
            #pragma unroll
            for (int d4 = 0; d4 < 8; d4++) {
                float4 vv = *(const float4*)&Vs[j][hf * 32 + d4 * 4];
                o[d4*4+0] = fmaf(p, vv.x, o[d4*4+0]);
                o[d4*4+1] = fmaf(p, vv.y, o[d4*4+1]);
                o[d4*4+2] = fmaf(p, vv.z, o[d4*4+2]);
                o[d4*4+3] = fmaf(p, vv.w, o[d4*4+3]);
            }
        }
        mrow = mnew;
    }

    const float inv = 1.f / lrow;
    const int qrow = q0 + row;
    float* obase = out + ((size_t)(b * SEQ + qrow)) * DMODEL + h * DHEAD + hf * 32;
    #pragma unroll
    for (int i = 0; i < 8; i++) {
        float4 vv = make_float4(o[i*4+0]*inv, o[i*4+1]*inv, o[i*4+2]*inv, o[i*4+3]*inv);
        *(float4*)&obase[i * 4] = vv;
    }
}

// ---------------------------------------------------------------------------

extern "C" void kernel_launch(void* const* d_in, const int* in_sizes, int n_in,
                              void* d_out, int out_size)
{
    (void)in_sizes; (void)n_in; (void)out_size;
    const float* x  = (const float*)d_in[0];
    const float* Wq = (const float*)d_in[1];
    const float* bq = (const float*)d_in[2];
    const float* Wk = (const float*)d_in[3];
    const float* bk = (const float*)d_in[4];
    const float* Wv = (const float*)d_in[5];
    const float* bv = (const float*)d_in[6];
    const float* Wo = (const float*)d_in[7];
    const float* bo = (const float*)d_in[8];
    float* out = (float*)d_out;

    float *pq, *pk, *pv, *patt;
    cudaGetSymbolAddress((void**)&pq,   g_q);
    cudaGetSymbolAddress((void**)&pk,   g_k);
    cudaGetSymbolAddress((void**)&pv,   g_v);
    cudaGetSymbolAddress((void**)&patt, g_att);

    dim3 gemm_grid(DMODEL / 64, MROWS / 128);   // (8, 64)
    gemm512<1><<<gemm_grid, 256>>>(x, Wq, bq, pq);
    gemm512<1><<<gemm_grid, 256>>>(x, Wk, bk, pk);
    gemm512<1><<<gemm_grid, 256>>>(x, Wv, bv, pv);

    dim3 attn_grid(SEQ / BQ, BATCH * NHEADS);   // (16, 32)
    attn_kernel<<<attn_grid, 256>>>(patt);

    gemm512<0><<<gemm_grid, 256>>>(patt, Wo, bo, out);
}

// round 10
// speedup vs baseline: 1.0014x; 1.0004x over previous
#include <cuda_runtime.h>
#include <math.h>

#define BATCH 4
#define SEQ   2048
#define DMODEL 512
#define NHEADS 8
#define DHEAD  64
#define MROWS (BATCH*SEQ)   // 8192

// Scratch (allocation-free rule: __device__ globals)
__device__ float g_q[BATCH*NHEADS*SEQ*DHEAD];   // [B,H,S,Dh]
__device__ float g_k[BATCH*NHEADS*SEQ*DHEAD];
__device__ float g_v[BATCH*NHEADS*SEQ*DHEAD];
__device__ float g_att[BATCH*SEQ*DMODEL];       // [B,S,D]

// ---------------------------------------------------------------------------
// GEMM: out = A[M,512] @ W[512,512] + bias
// MODE 0: out[m*512+n]   (plain, for O-projection into d_out)
// MODE 1: head-split scatter for Q/K/V: out[((b*H+h)*S+s)*64 + d]
// Tile: BM=128, BN=64, BK=32, 256 threads, 8x4 microtile per thread.
// ---------------------------------------------------------------------------
template<int MODE>
__global__ __launch_bounds__(256)
void gemm512(const float* __restrict__ A, const float* __restrict__ W,
             const float* __restrict__ bias, float* __restrict__ out)
{
    constexpr int BM = 128, BN = 64, BK = 32;
    __shared__ float As[BK][BM];   // transposed A tile
    __shared__ float Bs[BK][BN];

    const int tid = threadIdx.x;
    const int block_n = blockIdx.x * BN;
    const int block_m = blockIdx.y * BM;

    const int tn = (tid & 15) * 4;       // 0..60
    const int tm = (tid >> 4) * 8;       // 0..120

    const int a_row  = tid >> 3;         // 0..31 (then +i*32)
    const int a_col4 = (tid & 7) * 4;    // k offset 0..28
    const int b_row  = tid >> 4;         // 0..15 (then +i*16)
    const int b_col4 = (tid & 15) * 4;

    float acc[8][4];
    #pragma unroll
    for (int i = 0; i < 8; i++)
        #pragma unroll
        for (int j = 0; j < 4; j++) acc[i][j] = 0.f;

    for (int k0 = 0; k0 < DMODEL; k0 += BK) {
        __syncthreads();
        #pragma unroll
        for (int i = 0; i < 4; i++) {
            int m = a_row + i * 32;
            float4 v = *(const float4*)&A[(size_t)(block_m + m) * DMODEL + k0 + a_col4];
            As[a_col4 + 0][m] = v.x;
            As[a_col4 + 1][m] = v.y;
            As[a_col4 + 2][m] = v.z;
            As[a_col4 + 3][m] = v.w;
        }
        #pragma unroll
        for (int i = 0; i < 2; i++) {
            int kk = b_row + i * 16;
            *(float4*)&Bs[kk][b_col4] =
                *(const float4*)&W[(size_t)(k0 + kk) * DMODEL + block_n + b_col4];
        }
        __syncthreads();

        #pragma unroll
        for (int kk = 0; kk < BK; kk++) {
            float a[8], bf[4];
            *(float4*)&a[0] = *(const float4*)&As[kk][tm];
            *(float4*)&a[4] = *(const float4*)&As[kk][tm + 4];
            *(float4*)&bf[0] = *(const float4*)&Bs[kk][tn];
            #pragma unroll
            for (int i = 0; i < 8; i++)
                #pragma unroll
                for (int j = 0; j < 4; j++)
                    acc[i][j] = fmaf(a[i], bf[j], acc[i][j]);
        }
    }

    #pragma unroll
    for (int i = 0; i < 8; i++) {
        int m = block_m + tm + i;
        #pragma unroll
        for (int j = 0; j < 4; j++) {
            int n = block_n + tn + j;
            float val = acc[i][j] + bias[n];
            if (MODE == 0) {
                out[(size_t)m * DMODEL + n] = val;
            } else {
                int b = m / SEQ, s = m % SEQ;
                int h = n / DHEAD, d = n % DHEAD;
                out[(((size_t)(b * NHEADS + h)) * SEQ + s) * DHEAD + d] = val;
            }
        }
    }
}

// ---------------------------------------------------------------------------
// Flash-attention (streaming softmax), fp32.
// grid: (S/BQ, B*H), block: 256 threads.
// 2 threads per query row; each owns 32 of 64 output dims; Q row half + scores
// + output accumulators in registers; K/V tiles in SMEM (broadcast-friendly).
// Output written directly in [B,S,D] layout into g_att.
// ---------------------------------------------------------------------------
#define BQ 128
#define BKK 32

__global__ __launch_bounds__(256)
void attn_kernel(float* __restrict__ out)
{
    const int bh = blockIdx.y;             // 0..31
    const int b = bh / NHEADS, h = bh % NHEADS;
    const int q0 = blockIdx.x * BQ;
    const int tid = threadIdx.x;
    const int row = tid >> 1;              // 0..127
    const int hf  = tid & 1;               // half of Dh

    const float* Qbase = g_q + ((size_t)bh * SEQ + q0) * DHEAD;
    const float* Kbase = g_k + (size_t)bh * SEQ * DHEAD;
    const float* Vbase = g_v + (size_t)bh * SEQ * DHEAD;

    __shared__ float Ks[BKK][DHEAD];
    __shared__ float Vs[BKK][DHEAD];

    float qreg[32];
    #pragma unroll
    for (int i = 0; i < 8; i++)
        *(float4*)&qreg[i * 4] =
            *(const float4*)&Qbase[(size_t)row * DHEAD + hf * 32 + i * 4];

    float o[32];
    #pragma unroll
    for (int i = 0; i < 32; i++) o[i] = 0.f;
    float mrow = -1e30f, lrow = 0.f;
    const float scale = 0.04419417382415922f;   // 1/sqrt(512)

    for (int kb = 0; kb < SEQ; kb += BKK) {
        __syncthreads();
        // load K,V tile: 32x64 floats each -> 512 float4 each, 2 per thread
        #pragma unroll
        for (int i = 0; i < 2; i++) {
            int idx = tid + i * 256;       // float4 index 0..511
            int r = idx >> 4;              // 16 float4 per row
            int c = (idx & 15) * 4;
            *(float4*)&Ks[r][c] = *(const float4*)&Kbase[(size_t)(kb + r) * DHEAD + c];
            *(float4*)&Vs[r][c] = *(const float4*)&Vbase[(size_t)(kb + r) * DHEAD + c];
        }
        __syncthreads();

        float sc[BKK];
        float mblk = -1e30f;
        #pragma unroll
        for (int j = 0; j < BKK; j++) {
            float p = 0.f;
            #pragma unroll
            for (int d4 = 0; d4 < 8; d4++) {
                float4 kv = *(const float4*)&Ks[j][hf * 32 + d4 * 4];
                p = fmaf(qreg[d4*4+0], kv.x, p);
                p = fmaf(qreg[d4*4+1], kv.y, p);
                p = fmaf(qreg[d4*4+2], kv.z, p);
                p = fmaf(qreg[d4*4+3], kv.w, p);
            }
            p += __shfl_xor_sync(0xffffffffu, p, 1);   // combine the two halves
            p *= scale;
            sc[j] = p;
            mblk = fmaxf(mblk, p);
        }

        float mnew = fmaxf(mrow, mblk);
        float corr = __expf(mrow - mnew);
        lrow *= corr;
        #pragma unroll
        for (int i = 0; i < 32; i++) o[i] *= corr;

        #pragma unroll
        for (int j = 0; j < BKK; j++) {
            float p = __expf(sc[j] - mnew);
            lrow += p;
            #pragma unroll
            for (int d4 = 0; d4 < 8; d4++) {
                float4 vv = *(const float4*)&Vs[j][hf * 32 + d4 * 4];
                o[d4*4+0] = fmaf(p, vv.x, o[d4*4+0]);
                o[d4*4+1] = fmaf(p, vv.y, o[d4*4+1]);
                o[d4*4+2] = fmaf(p, vv.z, o[d4*4+2]);
                o[d4*4+3] = fmaf(p, vv.w, o[d4*4+3]);
            }
        }
        mrow = mnew;
    }

    const float inv = 1.f / lrow;
    const int qrow = q0 + row;
    float* obase = out + ((size_t)(b * SEQ + qrow)) * DMODEL + h * DHEAD + hf * 32;
    #pragma unroll
    for (int i = 0; i < 8; i++) {
        float4 vv = make_float4(o[i*4+0]*inv, o[i*4+1]*inv, o[i*4+2]*inv, o[i*4+3]*inv);
        *(float4*)&obase[i * 4] = vv;
    }
}

// ---------------------------------------------------------------------------

extern "C" void kernel_launch(void* const* d_in, const int* in_sizes, int n_in,
                              void* d_out, int out_size)
{
    (void)in_sizes; (void)n_in; (void)out_size;
    const float* x  = (const float*)d_in[0];
    const float* Wq = (const float*)d_in[1];
    const float* bq = (const float*)d_in[2];
    const float* Wk = (const float*)d_in[3];
    const float* bk = (const float*)d_in[4];
    const float* Wv = (const float*)d_in[5];
    const float* bv = (const float*)d_in[6];
    const float* Wo = (const float*)d_in[7];
    const float* bo = (const float*)d_in[8];
    float* out = (float*)d_out;

    float *pq, *pk, *pv, *patt;
    cudaGetSymbolAddress((void**)&pq,   g_q);
    cudaGetSymbolAddress((void**)&pk,   g_k);
    cudaGetSymbolAddress((void**)&pv,   g_v);
    cudaGetSymbolAddress((void**)&patt, g_att);

    dim3 gemm_grid(DMODEL / 64, MROWS / 128);   // (8, 64)
    gemm512<1><<<gemm_grid, 256>>>(x, Wq, bq, pq);
    gemm512<1><<<gemm_grid, 256>>>(x, Wk, bk, pk);
    gemm512<1><<<gemm_grid, 256>>>(x, Wv, bv, pv);

    dim3 attn_grid(SEQ / BQ, BATCH * NHEADS);   // (16, 32)
    attn_kernel<<<attn_grid, 256>>>(patt);

    gemm512<0><<<gemm_grid, 256>>>(patt, Wo, bo, out);
}

// round 11
// speedup vs baseline: 1.0018x; 1.0004x over previous
#include <cuda_runtime.h>
#include <math.h>

#define BATCH 4
#define SEQ   2048
#define DMODEL 512
#define NHEADS 8
#define DHEAD  64
#define MROWS (BATCH*SEQ)   // 8192

// Scratch (allocation-free rule: __device__ globals)
__device__ float g_q[BATCH*NHEADS*SEQ*DHEAD];   // [B,H,S,Dh]
__device__ float g_k[BATCH*NHEADS*SEQ*DHEAD];
__device__ float g_v[BATCH*NHEADS*SEQ*DHEAD];
__device__ float g_att[BATCH*SEQ*DMODEL];       // [B,S,D]

// ---------------------------------------------------------------------------
// GEMM: out = A[M,512] @ W[512,512] + bias
// MODE 0: out[m*512+n]   (plain, for O-projection into d_out)
// MODE 1: head-split scatter for Q/K/V: out[((b*H+h)*S+s)*64 + d]
// Tile: BM=128, BN=64, BK=32, 256 threads, 8x4 microtile per thread.
// ---------------------------------------------------------------------------
template<int MODE>
__global__ __launch_bounds__(256)
void gemm512(const float* __restrict__ A, const float* __restrict__ W,
             const float* __restrict__ bias, float* __restrict__ out)
{
    constexpr int BM = 128, BN = 64, BK = 32;
    __shared__ float As[BK][BM];   // transposed A tile
    __shared__ float Bs[BK][BN];

    const int tid = threadIdx.x;
    const int block_n = blockIdx.x * BN;
    const int block_m = blockIdx.y * BM;

    const int tn = (tid & 15) * 4;       // 0..60
    const int tm = (tid >> 4) * 8;       // 0..120

    const int a_row  = tid >> 3;         // 0..31 (then +i*32)
    const int a_col4 = (tid & 7) * 4;    // k offset 0..28
    const int b_row  = tid >> 4;         // 0..15 (then +i*16)
    const int b_col4 = (tid & 15) * 4;

    float acc[8][4];
    #pragma unroll
    for (int i = 0; i < 8; i++)
        #pragma unroll
        for (int j = 0; j < 4; j++) acc[i][j] = 0.f;

    for (int k0 = 0; k0 < DMODEL; k0 += BK) {
        __syncthreads();
        #pragma unroll
        for (int i = 0; i < 4; i++) {
            int m = a_row + i * 32;
            float4 v = *(const float4*)&A[(size_t)(block_m + m) * DMODEL + k0 + a_col4];
            As[a_col4 + 0][m] = v.x;
            As[a_col4 + 1][m] = v.y;
            As[a_col4 + 2][m] = v.z;
            As[a_col4 + 3][m] = v.w;
        }
        #pragma unroll
        for (int i = 0; i < 2; i++) {
            int kk = b_row + i * 16;
            *(float4*)&Bs[kk][b_col4] =
                *(const float4*)&W[(size_t)(k0 + kk) * DMODEL + block_n + b_col4];
        }
        __syncthreads();

        #pragma unroll
        for (int kk = 0; kk < BK; kk++) {
            float a[8], bf[4];
            *(float4*)&a[0] = *(const float4*)&As[kk][tm];
            *(float4*)&a[4] = *(const float4*)&As[kk][tm + 4];
            *(float4*)&bf[0] = *(const float4*)&Bs[kk][tn];
            #pragma unroll
            for (int i = 0; i < 8; i++)
                #pragma unroll
                for (int j = 0; j < 4; j++)
                    acc[i][j] = fmaf(a[i], bf[j], acc[i][j]);
        }
    }

    #pragma unroll
    for (int i = 0; i < 8; i++) {
        int m = block_m + tm + i;
        #pragma unroll
        for (int j = 0; j < 4; j++) {
            int n = block_n + tn + j;
            float val = acc[i][j] + bias[n];
            if (MODE == 0) {
                out[(size_t)m * DMODEL + n] = val;
            } else {
                int b = m / SEQ, s = m % SEQ;
                int h = n / DHEAD, d = n % DHEAD;
                out[(((size_t)(b * NHEADS + h)) * SEQ + s) * DHEAD + d] = val;
            }
        }
    }
}

// ---------------------------------------------------------------------------
// Flash-attention (streaming softmax), fp32.
// grid: (S/BQ, B*H), block: 256 threads.
// 2 threads per query row; each owns 32 of 64 output dims; Q row half + scores
// + output accumulators in registers; K/V tiles in SMEM (broadcast-friendly).
// Output written directly in [B,S,D] layout into g_att.
// ---------------------------------------------------------------------------
#define BQ 128
#define BKK 32

__global__ __launch_bounds__(256)
void attn_kernel(float* __restrict__ out)
{
    const int bh = blockIdx.y;             // 0..31
    const int b = bh / NHEADS, h = bh % NHEADS;
    const int q0 = blockIdx.x * BQ;
    const int tid = threadIdx.x;
    const int row = tid >> 1;              // 0..127
    const int hf  = tid & 1;               // half of Dh

    const float* Qbase = g_q + ((size_t)bh * SEQ + q0) * DHEAD;
    const float* Kbase = g_k + (size_t)bh * SEQ * DHEAD;
    const float* Vbase = g_v + (size_t)bh * SEQ * DHEAD;

    __shared__ float Ks[BKK][DHEAD];
    __shared__ float Vs[BKK][DHEAD];

    float qreg[32];
    #pragma unroll
    for (int i = 0; i < 8; i++)
        *(float4*)&qreg[i * 4] =
            *(const float4*)&Qbase[(size_t)row * DHEAD + hf * 32 + i * 4];

    float o[32];
    #pragma unroll
    for (int i = 0; i < 32; i++) o[i] = 0.f;
    float mrow = -1e30f, lrow = 0.f;
    const float scale = 0.04419417382415922f;   // 1/sqrt(512)

    for (int kb = 0; kb < SEQ; kb += BKK) {
        __syncthreads();
        // load K,V tile: 32x64 floats each -> 512 float4 each, 2 per thread
        #pragma unroll
        for (int i = 0; i < 2; i++) {
            int idx = tid + i * 256;       // float4 index 0..511
            int r = idx >> 4;              // 16 float4 per row
            int c = (idx & 15) * 4;
            *(float4*)&Ks[r][c] = *(const float4*)&Kbase[(size_t)(kb + r) * DHEAD + c];
            *(float4*)&Vs[r][c] = *(const float4*)&Vbase[(size_t)(kb + r) * DHEAD + c];
        }
        __syncthreads();

        float sc[BKK];
        float mblk = -1e30f;
        #pragma unroll
        for (int j = 0; j < BKK; j++) {
            float p = 0.f;
            #pragma unroll
            for (int d4 = 0; d4 < 8; d4++) {
                float4 kv = *(const float4*)&Ks[j][hf * 32 + d4 * 4];
                p = fmaf(qreg[d4*4+0], kv.x, p);
                p = fmaf(qreg[d4*4+1], kv.y, p);
                p = fmaf(qreg[d4*4+2], kv.z, p);
                p = fmaf(qreg[d4*4+3], kv.w, p);
            }
            p += __shfl_xor_sync(0xffffffffu, p, 1);   // combine the two halves
            p *= scale;
            sc[j] = p;
            mblk = fmaxf(mblk, p);
        }

        float mnew = fmaxf(mrow, mblk);
        float corr = __expf(mrow - mnew);
        lrow *= corr;
        #pragma unroll
        for (int i = 0; i < 32; i++) o[i] *= corr;

        #pragma unroll
        for (int j = 0; j < BKK; j++) {
            float p = __expf(sc[j] - mnew);
            lrow += p;
            #pragma unroll
            for (int d4 = 0; d4 < 8; d4++) {
                float4 vv = *(const float4*)&Vs[j][hf * 32 + d4 * 4];
                o[d4*4+0] = fmaf(p, vv.x, o[d4*4+0]);
                o[d4*4+1] = fmaf(p, vv.y, o[d4*4+1]);
                o[d4*4+2] = fmaf(p, vv.z, o[d4*4+2]);
                o[d4*4+3] = fmaf(p, vv.w, o[d4*4+3]);
            }
        }
        mrow = mnew;
    }

    const float inv = 1.f / lrow;
    const int qrow = q0 + row;
    float* obase = out + ((size_t)(b * SEQ + qrow)) * DMODEL + h * DHEAD + hf * 32;
    #pragma unroll
    for (int i = 0; i < 8; i++) {
        float4 vv = make_float4(o[i*4+0]*inv, o[i*4+1]*inv, o[i*4+2]*inv, o[i*4+3]*inv);
        *(float4*)&obase[i * 4] = vv;
    }
}

// ---------------------------------------------------------------------------

extern "C" void kernel_launch(void* const* d_in, const int* in_sizes, int n_in,
                              void* d_out, int out_size)
{
    (void)in_sizes; (void)n_in; (void)out_size;
    const float* x  = (const float*)d_in[0];
    const float* Wq = (const float*)d_in[1];
    const float* bq = (const float*)d_in[2];
    const float* Wk = (const float*)d_in[3];
    const float* bk = (const float*)d_in[4];
    const float* Wv = (const float*)d_in[5];
    const float* bv = (const float*)d_in[6];
    const float* Wo = (const float*)d_in[7];
    const float* bo = (const float*)d_in[8];
    float* out = (float*)d_out;

    float *pq, *pk, *pv, *patt;
    cudaGetSymbolAddress((void**)&pq,   g_q);
    cudaGetSymbolAddress((void**)&pk,   g_k);
    cudaGetSymbolAddress((void**)&pv,   g_v);
    cudaGetSymbolAddress((void**)&patt, g_att);

    dim3 gemm_grid(DMODEL / 64, MROWS / 128);   // (8, 64)
    gemm512<1><<<gemm_grid, 256>>>(x, Wq, bq, pq);
    gemm512<1><<<gemm_grid, 256>>>(x, Wk, bk, pk);
    gemm512<1><<<gemm_grid, 256>>>(x, Wv, bv, pv);

    dim3 attn_grid(SEQ / BQ, BATCH * NHEADS);   // (16, 32)
    attn_kernel<<<attn_grid, 256>>>(patt);

    gemm512<0><<<gemm_grid, 256>>>(patt, Wo, bo, out);
}